// round 6
// baseline (speedup 1.0000x reference)
#include <cuda_runtime.h>
#include <cuda_bf16.h>
#include <cstdint>

// ===========================================================================
// SwinWindowAttention — all-HMMA pipeline (compute_100-safe)
//   wprep        : qkv_w/proj_w -> transposed bf16 hi/lo
//   gemm_mma<0>  : QKV = x @ qkv_w + b   (bf16 3-pass split, fp32 acc)
//   attn_mma     : per-(window,head) attention on mma.sync (3-pass splits)
//   gemm_mma<1>  : out = O @ proj_w + b
// ===========================================================================

#define SCALE_Q 0.17677669529663687f
#define NWIN    2048
#define TOKENS  100352            // 2048*49
#define MTILES  784               // TOKENS/128
#define ASTRIDE 136               // A smem row stride (halfs)
#define BSTRIDE 72                // B half-chunk smem row stride (halfs)

// ---- device scratch (static: no allocation) -------------------------------
__device__ __nv_bfloat16 g_wqkvT_hi[384 * 128];
__device__ __nv_bfloat16 g_wqkvT_lo[384 * 128];
__device__ __nv_bfloat16 g_wprojT_hi[128 * 128];
__device__ __nv_bfloat16 g_wprojT_lo[128 * 128];
__device__ float g_q[NWIN * 4 * 49 * 32];
__device__ float g_k[NWIN * 4 * 49 * 32];
__device__ float g_v[NWIN * 4 * 49 * 32];
__device__ float g_o[(size_t)TOKENS * 128];

// ---- helpers --------------------------------------------------------------
static __device__ __forceinline__ uint32_t smem_u32(const void* p) {
    uint32_t a;
    asm("{.reg .u64 t; cvta.to.shared.u64 t, %1; cvt.u32.u64 %0, t;}"
        : "=r"(a) : "l"(p));
    return a;
}
static __device__ __forceinline__ uint32_t pkbf(float a, float b) {
    __nv_bfloat162 t = __floats2bfloat162_rn(a, b);
    return *reinterpret_cast<uint32_t*>(&t);
}
static __device__ __forceinline__ void ldmx4(uint32_t* r, uint32_t a) {
    asm volatile("ldmatrix.sync.aligned.m8n8.x4.shared.b16 {%0,%1,%2,%3}, [%4];"
                 : "=r"(r[0]), "=r"(r[1]), "=r"(r[2]), "=r"(r[3]) : "r"(a));
}
static __device__ __forceinline__ void mma16816(float* d, const uint32_t* a,
                                                const uint32_t* b) {
    asm volatile("mma.sync.aligned.m16n8k16.row.col.f32.bf16.bf16.f32 "
                 "{%0,%1,%2,%3}, {%4,%5,%6,%7}, {%8,%9}, {%0,%1,%2,%3};"
                 : "+f"(d[0]), "+f"(d[1]), "+f"(d[2]), "+f"(d[3])
                 : "r"(a[0]), "r"(a[1]), "r"(a[2]), "r"(a[3]),
                   "r"(b[0]), "r"(b[1]));
}

// ===========================================================================
// Kernel 0: weight prep (transpose + bf16 hi/lo split)
// ===========================================================================
__global__ void wprep(const float* __restrict__ qkvw,
                      const float* __restrict__ projw) {
    int i = blockIdx.x * 256 + threadIdx.x;
    if (i < 384 * 128) {
        int n = i >> 7, k = i & 127;
        float w = qkvw[k * 384 + n];
        __nv_bfloat16 h = __float2bfloat16_rn(w);
        g_wqkvT_hi[i] = h;
        g_wqkvT_lo[i] = __float2bfloat16_rn(w - __bfloat162float(h));
    }
    if (i < 128 * 128) {
        int n = i >> 7, k = i & 127;
        float w = projw[k * 128 + n];
        __nv_bfloat16 h = __float2bfloat16_rn(w);
        g_wprojT_hi[i] = h;
        g_wprojT_lo[i] = __float2bfloat16_rn(w - __bfloat162float(h));
    }
}

// ===========================================================================
// Kernels 1 & 3: bf16-split GEMM via mma.sync
//   CTA 128x128 out tile, 8 warps (warp = 32x64).  A full-K resident; B is
//   staged in K-halves (smem 104 KB -> 2 CTAs/SM).
// ===========================================================================
#define SM_A_BYTES (2 * 128 * ASTRIDE * 2)             // Ah+Al  = 69632
#define SM_B_BYTES (2 * 128 * BSTRIDE * 2)             // Bh+Bl  = 36864
#define SM_GEMM_BYTES (SM_A_BYTES + SM_B_BYTES)        // 106496

template<int MODE>
__global__ void __launch_bounds__(256, 2)
gemm_mma_kernel(const float* __restrict__ Ain,
                const float* __restrict__ bias,
                float* __restrict__ outp)
{
    constexpr int NC = (MODE == 0) ? 3 : 1;
    const __nv_bfloat16* __restrict__ Bhig = (MODE == 0) ? g_wqkvT_hi : g_wprojT_hi;
    const __nv_bfloat16* __restrict__ Blog = (MODE == 0) ? g_wqkvT_lo : g_wprojT_lo;
    const float* __restrict__ A = (MODE == 0) ? Ain : g_o;

    extern __shared__ __nv_bfloat16 smh[];
    __nv_bfloat16* Ah = smh;
    __nv_bfloat16* Al = smh + 128 * ASTRIDE;
    __nv_bfloat16* Bh = smh + 2 * 128 * ASTRIDE;
    __nv_bfloat16* Bl = Bh + 128 * BSTRIDE;

    const int t = threadIdx.x, wid = t >> 5, lane = t & 31;
    const int tile = blockIdx.x;

    // ---- A tile: 128x128 fp32 -> bf16 hi/lo in smem -----------------------
    const float4* a4 = reinterpret_cast<const float4*>(A) + (size_t)tile * 4096;
    #pragma unroll
    for (int it = 0; it < 16; it++) {
        int idx = t + it * 256;                 // 0..4095
        int r = idx >> 5, k = (idx & 31) * 4;
        float4 xv = a4[idx];
        __nv_bfloat16 b0 = __float2bfloat16_rn(xv.x), b1 = __float2bfloat16_rn(xv.y),
                      b2 = __float2bfloat16_rn(xv.z), b3 = __float2bfloat16_rn(xv.w);
        uint2 hi = make_uint2(pkbf(__bfloat162float(b0), __bfloat162float(b1)),
                              pkbf(__bfloat162float(b2), __bfloat162float(b3)));
        uint2 lo = make_uint2(pkbf(xv.x - __bfloat162float(b0), xv.y - __bfloat162float(b1)),
                              pkbf(xv.z - __bfloat162float(b2), xv.w - __bfloat162float(b3)));
        *reinterpret_cast<uint2*>(&Ah[r * ASTRIDE + k]) = hi;
        *reinterpret_cast<uint2*>(&Al[r * ASTRIDE + k]) = lo;
    }

    // warp tiling
    const int wr = wid >> 1, wc = wid & 1;
    const int m0 = wr * 32, n0 = wc * 64;
    const int arow = lane & 15,  aco = (lane & 16) ? 8 : 0;
    const int brow = (lane & 7) + ((lane & 16) ? 8 : 0), bco = (lane & 8) ? 8 : 0;
    const int g = lane >> 2, tig2 = (lane & 3) * 2;

    for (int nc = 0; nc < NC; nc++) {
        float acc[2][8][4];
        #pragma unroll
        for (int tm = 0; tm < 2; tm++)
            #pragma unroll
            for (int tn = 0; tn < 8; tn++)
                #pragma unroll
                for (int e = 0; e < 4; e++) acc[tm][tn][e] = 0.f;

        for (int kh = 0; kh < 2; kh++) {
            __syncthreads();   // previous compute (or A stores) done
            // ---- B half-chunk: 128 rows (N) x 64 (K) hi/lo ----------------
            const uint4* bh4 = reinterpret_cast<const uint4*>(Bhig);
            const uint4* bl4 = reinterpret_cast<const uint4*>(Blog);
            #pragma unroll
            for (int it = 0; it < 4; it++) {
                int idx = t + it * 256;          // 0..1023
                int n = idx >> 3, kk = idx & 7;  // uint4 = 8 halfs
                int src = (nc * 128 + n) * 16 + kh * 8 + kk;
                *reinterpret_cast<uint4*>(&Bh[n * BSTRIDE + kk * 8]) = bh4[src];
                *reinterpret_cast<uint4*>(&Bl[n * BSTRIDE + kk * 8]) = bl4[src];
            }
            __syncthreads();

            #pragma unroll
            for (int pass = 0; pass < 3; pass++) {      // hh, hl, lh
                const __nv_bfloat16* Ap = (pass == 2) ? Al : Ah;
                const __nv_bfloat16* Bp = (pass == 1) ? Bl : Bh;
                const uint32_t abase = smem_u32(Ap + (m0 + arow) * ASTRIDE
                                                + kh * 64 + aco);
                const uint32_t bbase = smem_u32(Bp + (n0 + brow) * BSTRIDE + bco);
                #pragma unroll
                for (int ks = 0; ks < 4; ks++) {        // k16 steps in half
                    const uint32_t koff = (uint32_t)(ks * 32);
                    uint32_t af[2][4], bf[4][4];
                    ldmx4(af[0], abase + koff);
                    ldmx4(af[1], abase + 16 * ASTRIDE * 2 + koff);
                    #pragma unroll
                    for (int tb = 0; tb < 4; tb++)
                        ldmx4(bf[tb], bbase + tb * 16 * BSTRIDE * 2 + koff);
                    #pragma unroll
                    for (int tm = 0; tm < 2; tm++)
                        #pragma unroll
                        for (int tn = 0; tn < 8; tn++)
                            mma16816(acc[tm][tn], af[tm], &bf[tn >> 1][(tn & 1) * 2]);
                }
            }
        }

        // ---- epilogue: regs -> gmem ---------------------------------------
        #pragma unroll
        for (int tm = 0; tm < 2; tm++) {
            #pragma unroll
            for (int tn = 0; tn < 8; tn++) {
                const int col = n0 + tn * 8 + tig2;
                float2 b2v = __ldg(reinterpret_cast<const float2*>(
                                   bias + (MODE == 0 ? nc * 128 : 0) + col));
                #pragma unroll
                for (int hh = 0; hh < 2; hh++) {
                    const int m = m0 + tm * 16 + g + hh * 8;
                    const int token = tile * 128 + m;
                    float vx = acc[tm][tn][hh * 2 + 0] + b2v.x;
                    float vy = acc[tm][tn][hh * 2 + 1] + b2v.y;
                    if (MODE == 0) {
                        const uint32_t win = (uint32_t)token / 49u;
                        const uint32_t nt  = (uint32_t)token - win * 49u;
                        const int head = col >> 5, d = col & 31;
                        float* dst0 = (nc == 0) ? g_q : (nc == 1) ? g_k : g_v;
                        float* dst = dst0 + ((size_t)(win * 4 + head) * 49 + nt) * 32 + d;
                        const float s = (nc == 0) ? SCALE_Q : 1.0f;
                        *reinterpret_cast<float2*>(dst) = make_float2(vx * s, vy * s);
                    } else {
                        float* dst = outp + (size_t)token * 128 + col;
                        *reinterpret_cast<float2*>(dst) = make_float2(vx, vy);
                    }
                }
            }
        }
    }
}

// ===========================================================================
// Kernel 2: tensor-core attention.  CTA = one (window, head), 4 warps.
//   S[64,64] = q @ k^T (3-pass bf16 split), softmax in fragments,
//   O[64,32] = P @ vT  (3-pass bf16 split).
// ===========================================================================
__global__ void __launch_bounds__(128, 4)
attn_mma_kernel(const float* __restrict__ maskg, const float* __restrict__ relg)
{
    __shared__ __nv_bfloat16 qh[64 * 40], ql[64 * 40];
    __shared__ __nv_bfloat16 kh_[64 * 40], kl_[64 * 40];
    __shared__ __nv_bfloat16 vth[32 * 72], vtl[32 * 72];
    __shared__ float rel_s[176];
    __shared__ __nv_bfloat16 ph[64 * 72], pl[64 * 72];

    const int t = threadIdx.x, wid = t >> 5, lane = t & 31;
    const int win = blockIdx.x >> 2;
    const int h = blockIdx.x & 3;
    const int w63 = win & 63;
    const size_t base = ((size_t)win * 4 + h) * 1568;

    // ---- load q, k (hi/lo, stride 40) -------------------------------------
    const float4* qg4 = reinterpret_cast<const float4*>(g_q + base);
    const float4* kg4 = reinterpret_cast<const float4*>(g_k + base);
    #pragma unroll
    for (int it = 0; it < 4; it++) {
        int idx = t + it * 128;
        if (idx < 392) {
            int r = idx >> 3, c4 = (idx & 7) * 4;
            float4 qv = qg4[idx];
            __nv_bfloat16 q0 = __float2bfloat16_rn(qv.x), q1 = __float2bfloat16_rn(qv.y),
                          q2 = __float2bfloat16_rn(qv.z), q3 = __float2bfloat16_rn(qv.w);
            *reinterpret_cast<uint2*>(&qh[r * 40 + c4]) =
                make_uint2(pkbf(__bfloat162float(q0), __bfloat162float(q1)),
                           pkbf(__bfloat162float(q2), __bfloat162float(q3)));
            *reinterpret_cast<uint2*>(&ql[r * 40 + c4]) =
                make_uint2(pkbf(qv.x - __bfloat162float(q0), qv.y - __bfloat162float(q1)),
                           pkbf(qv.z - __bfloat162float(q2), qv.w - __bfloat162float(q3)));
            float4 kv = kg4[idx];
            __nv_bfloat16 k0 = __float2bfloat16_rn(kv.x), k1 = __float2bfloat16_rn(kv.y),
                          k2 = __float2bfloat16_rn(kv.z), k3 = __float2bfloat16_rn(kv.w);
            *reinterpret_cast<uint2*>(&kh_[r * 40 + c4]) =
                make_uint2(pkbf(__bfloat162float(k0), __bfloat162float(k1)),
                           pkbf(__bfloat162float(k2), __bfloat162float(k3)));
            *reinterpret_cast<uint2*>(&kl_[r * 40 + c4]) =
                make_uint2(pkbf(kv.x - __bfloat162float(k0), kv.y - __bfloat162float(k1)),
                           pkbf(kv.z - __bfloat162float(k2), kv.w - __bfloat162float(k3)));
        }
    }
    // ---- v transposed into [d][j] (hi/lo, stride 72) ----------------------
    const float* vg = g_v + base;
    #pragma unroll
    for (int it = 0; it < 13; it++) {
        int idx = t + it * 128;
        if (idx < 1568) {
            int j = idx >> 5, d = idx & 31;
            float val = vg[idx];
            __nv_bfloat16 hi = __float2bfloat16_rn(val);
            vth[d * 72 + j] = hi;
            vtl[d * 72 + j] = __float2bfloat16_rn(val - __bfloat162float(hi));
        }
    }
    // zero vT pad cols j = 49..63
    #pragma unroll
    for (int it = 0; it < 4; it++) {
        int idx = t + it * 128;           // 0..511
        int d = idx >> 4, jj = 48 + (idx & 15);
        if (jj > 48) {
            vth[d * 72 + jj] = __float2bfloat16_rn(0.f);
            vtl[d * 72 + jj] = __float2bfloat16_rn(0.f);
        }
    }
    if (t < 169)       rel_s[t] = relg[t * 4 + h];
    if (t + 128 < 169) rel_s[t + 128] = relg[(t + 128) * 4 + h];
    __syncthreads();

    // ---- S = q @ k^T  (warp w: rows m0..m0+15, cols 0..63) ----------------
    const int m0 = wid * 16;
    const int arow = lane & 15, aco = (lane & 16) ? 8 : 0;
    const int brow = (lane & 7) + ((lane & 16) ? 8 : 0), bco = (lane & 8) ? 8 : 0;
    const int g = lane >> 2, qd = lane & 3;

    float acc[8][4];
    #pragma unroll
    for (int tn = 0; tn < 8; tn++)
        #pragma unroll
        for (int e = 0; e < 4; e++) acc[tn][e] = 0.f;

    #pragma unroll
    for (int pass = 0; pass < 3; pass++) {
        const __nv_bfloat16* Ap = (pass == 2) ? ql : qh;
        const __nv_bfloat16* Bp = (pass == 1) ? kl_ : kh_;
        const uint32_t ab = smem_u32(Ap + (m0 + arow) * 40 + aco);
        const uint32_t bb = smem_u32(Bp + brow * 40 + bco);
        #pragma unroll
        for (int ks = 0; ks < 2; ks++) {
            const uint32_t koff = (uint32_t)(ks * 32);
            uint32_t af[4], bf[4][4];
            ldmx4(af, ab + koff);
            #pragma unroll
            for (int tb = 0; tb < 4; tb++)
                ldmx4(bf[tb], bb + tb * 16 * 80 + koff);
            #pragma unroll
            for (int tn = 0; tn < 8; tn++)
                mma16816(acc[tn], af, &bf[tn >> 1][(tn & 1) * 2]);
        }
    }

    // ---- bias + mask + softmax in fragments; P -> smem (hi/lo) ------------
    #pragma unroll
    for (int hh = 0; hh < 2; hh++) {
        const int i = m0 + g + hh * 8;
        const bool rowok = (i < 49);
        const int ii = rowok ? i : 0;
        const int iy = ii / 7, ix = ii - iy * 7;
        const float* mrow = maskg + ((size_t)(w63 * 49 + ii)) * 49;

        float m = -3.0e38f;
        #pragma unroll
        for (int tn = 0; tn < 8; tn++)
            #pragma unroll
            for (int e2 = 0; e2 < 2; e2++) {
                const int j = tn * 8 + qd * 2 + e2;
                float lv = -1.0e30f;
                if (j < 49) {
                    const int jy = j / 7, jx = j - jy * 7;
                    lv = acc[tn][hh * 2 + e2]
                       + rel_s[(iy - jy + 6) * 13 + (ix - jx + 6)]
                       + __ldg(&mrow[j]);
                }
                acc[tn][hh * 2 + e2] = lv;
                m = fmaxf(m, lv);
            }
        m = fmaxf(m, __shfl_xor_sync(0xFFFFFFFFu, m, 1));
        m = fmaxf(m, __shfl_xor_sync(0xFFFFFFFFu, m, 2));
        float ssum = 0.f;
        #pragma unroll
        for (int tn = 0; tn < 8; tn++)
            #pragma unroll
            for (int e2 = 0; e2 < 2; e2++) {
                float e = __expf(acc[tn][hh * 2 + e2] - m);
                acc[tn][hh * 2 + e2] = e;
                ssum += e;
            }
        ssum += __shfl_xor_sync(0xFFFFFFFFu, ssum, 1);
        ssum += __shfl_xor_sync(0xFFFFFFFFu, ssum, 2);
        const float inv = 1.0f / ssum;
        #pragma unroll
        for (int tn = 0; tn < 8; tn++) {
            float p0 = acc[tn][hh * 2 + 0] * inv;
            float p1 = acc[tn][hh * 2 + 1] * inv;
            __nv_bfloat16 h0 = __float2bfloat16_rn(p0), h1 = __float2bfloat16_rn(p1);
            const int off = i * 72 + tn * 8 + qd * 2;
            *reinterpret_cast<uint32_t*>(&ph[off]) =
                pkbf(__bfloat162float(h0), __bfloat162float(h1));
            *reinterpret_cast<uint32_t*>(&pl[off]) =
                pkbf(p0 - __bfloat162float(h0), p1 - __bfloat162float(h1));
        }
    }
    __syncwarp();

    // ---- O = P @ vT  (n = 32 head dims) -----------------------------------
    float accO[4][4];
    #pragma unroll
    for (int tn = 0; tn < 4; tn++)
        #pragma unroll
        for (int e = 0; e < 4; e++) accO[tn][e] = 0.f;

    #pragma unroll
    for (int pass = 0; pass < 3; pass++) {
        const __nv_bfloat16* Ap = (pass == 2) ? pl : ph;
        const __nv_bfloat16* Bp = (pass == 1) ? vtl : vth;
        const uint32_t ab = smem_u32(Ap + (m0 + arow) * 72 + aco);
        const uint32_t bb = smem_u32(Bp + brow * 72 + bco);
        #pragma unroll
        for (int ks = 0; ks < 4; ks++) {
            const uint32_t koff = (uint32_t)(ks * 32);
            uint32_t af[4], bf[2][4];
            ldmx4(af, ab + koff);
            ldmx4(bf[0], bb + koff);
            ldmx4(bf[1], bb + 16 * 144 + koff);
            #pragma unroll
            for (int tn = 0; tn < 4; tn++)
                mma16816(accO[tn], af, &bf[tn >> 1][(tn & 1) * 2]);
        }
    }

    // ---- write O rows i < 49 ----------------------------------------------
    #pragma unroll
    for (int hh = 0; hh < 2; hh++) {
        const int i = m0 + g + hh * 8;
        if (i < 49) {
            float* orow = g_o + ((size_t)win * 49 + i) * 128 + h * 32;
            #pragma unroll
            for (int tn = 0; tn < 4; tn++) {
                const int d = tn * 8 + qd * 2;
                *reinterpret_cast<float2*>(&orow[d]) =
                    make_float2(accO[tn][hh * 2 + 0], accO[tn][hh * 2 + 1]);
            }
        }
    }
}

// ===========================================================================
extern "C" void kernel_launch(void* const* d_in, const int* in_sizes, int n_in,
                              void* d_out, int out_size)
{
    const float* x      = (const float*)d_in[0];
    const float* mask   = (const float*)d_in[1];
    const float* qkv_w  = (const float*)d_in[2];
    const float* qkv_b  = (const float*)d_in[3];
    const float* proj_w = (const float*)d_in[4];
    const float* proj_b = (const float*)d_in[5];
    const float* rel    = (const float*)d_in[6];
    float* out = (float*)d_out;

    cudaFuncSetAttribute(gemm_mma_kernel<0>,
                         cudaFuncAttributeMaxDynamicSharedMemorySize, SM_GEMM_BYTES);
    cudaFuncSetAttribute(gemm_mma_kernel<1>,
                         cudaFuncAttributeMaxDynamicSharedMemorySize, SM_GEMM_BYTES);

    wprep<<<192, 256>>>(qkv_w, proj_w);
    gemm_mma_kernel<0><<<MTILES, 256, SM_GEMM_BYTES>>>(x, qkv_b, nullptr);
    attn_mma_kernel<<<NWIN * 4, 128>>>(mask, rel);
    gemm_mma_kernel<1><<<MTILES, 256, SM_GEMM_BYTES>>>(nullptr, proj_b, out);
}